// round 15
// baseline (speedup 1.0000x reference)
#include <cuda_runtime.h>
#include <cuda_bf16.h>
#include <math.h>

#define NB   2
#define CH   64
#define HT   128
#define WD   128
#define HW   16384
#define C3   192
#define C4   256

typedef unsigned long long u64;

// ---------------- scratch (device globals; no allocation allowed) ----------
__device__ float g_qkv[NB * HW * C3];   // [token][192] (q pre-scaled)
__device__ float g_aout[NB * HW * CH];  // attention output, token-major
__device__ float g_w2t[C4 * CH];        // fc2_w transposed [256][64] (k-major)

__device__ __forceinline__ float warp_sum(float v) {
#pragma unroll
    for (int o = 16; o; o >>= 1) v += __shfl_xor_sync(0xffffffffu, v, o);
    return v;
}
__device__ __forceinline__ float warp_max(float v) {
#pragma unroll
    for (int o = 16; o; o >>= 1) v = fmaxf(v, __shfl_xor_sync(0xffffffffu, v, o));
    return v;
}
__device__ __forceinline__ u64 pk2(float v) {
    u64 r; asm("mov.b64 %0,{%1,%1};" : "=l"(r) : "f"(v)); return r;
}
__device__ __forceinline__ u64 pk2f(float a, float b) {
    u64 r; asm("mov.b64 %0,{%1,%2};" : "=l"(r) : "f"(a), "f"(b)); return r;
}
__device__ __forceinline__ void fma2(u64& d, u64 a, u64 b) {
    asm("fma.rn.f32x2 %0,%1,%2,%0;" : "+l"(d) : "l"(a), "l"(b));
}
__device__ __forceinline__ float2 up2(u64 v) {
    float2 f; asm("mov.b64 {%0,%1},%2;" : "=f"(f.x), "=f"(f.y) : "l"(v)); return f;
}
__device__ __forceinline__ void cpa4(void* s, const void* g) {
    unsigned sa = (unsigned)__cvta_generic_to_shared(s);
    asm volatile("cp.async.ca.shared.global [%0], [%1], 4;" :: "r"(sa), "l"(g));
}
__device__ __forceinline__ void cp_commit() { asm volatile("cp.async.commit_group;"); }
__device__ __forceinline__ void cp_wait0()  { asm volatile("cp.async.wait_group 0;"); }

// fast GELU (HW tanh.approx)
__device__ __forceinline__ float gelu_f(float x) {
    float t = x * x;
    float u = fmaf(t, 0.03567740814183373f, 0.7978845608028654f);
    float a = x * u;
    float th; asm("tanh.approx.f32 %0,%1;" : "=f"(th) : "f"(a));
    float hx = 0.5f * x;
    return fmaf(hx, th, hx);
}

// ============================================================================
// K1: [blocks 0-63: fc2 transpose] + LN1 + QKV GEMM (weights [o][70], LDS.64).
// ============================================================================
__global__ __launch_bounds__(256, 3) void k_ln_qkv(
    const float* __restrict__ x, const float* __restrict__ qkv_w,
    const float* __restrict__ qkv_b, const float* __restrict__ ln_w,
    const float* __restrict__ ln_b, const float* __restrict__ fc2_w)
{
    extern __shared__ float sm[];
    float* xn = sm;                 // [64][68] normalized, k-major
    float* W  = sm + 4352;          // [192][70] row-major, stride 70

    const int tid = threadIdx.x, warp = tid >> 5, lane = tid & 31;
    const int n = blockIdx.x >> 8;
    const int hw0 = (blockIdx.x & 255) << 6;
    const int t0 = warp * 8;
    const float* xin = x + (size_t)n * CH * HW + hw0 + t0;

    if (blockIdx.x < 64) {
        int i = blockIdx.x * 256 + tid;
        int c = i >> 8, k = i & 255;
        g_w2t[k * 64 + c] = fc2_w[i];
    }

    for (int idx = tid; idx < C3 * 64; idx += 256) {
        int o = idx >> 6, k = idx & 63;
        cpa4(&W[o * 70 + k], &qkv_w[idx]);
    }
    cp_commit();

    float xc0[8], xc1[8];
    {
        float4 a = *(const float4*)&xin[(size_t)lane * HW];
        float4 b = *(const float4*)&xin[(size_t)lane * HW + 4];
        xc0[0]=a.x; xc0[1]=a.y; xc0[2]=a.z; xc0[3]=a.w;
        xc0[4]=b.x; xc0[5]=b.y; xc0[6]=b.z; xc0[7]=b.w;
        float4 c = *(const float4*)&xin[(size_t)(lane + 32) * HW];
        float4 d = *(const float4*)&xin[(size_t)(lane + 32) * HW + 4];
        xc1[0]=c.x; xc1[1]=c.y; xc1[2]=c.z; xc1[3]=c.w;
        xc1[4]=d.x; xc1[5]=d.y; xc1[6]=d.z; xc1[7]=d.w;
    }
    float lw0 = ln_w[lane], lb0 = ln_b[lane];
    float lw1 = ln_w[lane + 32], lb1 = ln_b[lane + 32];
#pragma unroll
    for (int t = 0; t < 8; t++) {
        float c0 = xc0[t], c1 = xc1[t];
        float s  = warp_sum(c0 + c1);
        float sq = warp_sum(c0 * c0 + c1 * c1);
        float m  = s * (1.0f / 64.0f);
        float r  = rsqrtf(sq * (1.0f / 64.0f) - m * m + 1e-5f);
        xn[lane * 68 + t0 + t]        = (c0 - m) * r * lw0 + lb0;
        xn[(lane + 32) * 68 + t0 + t] = (c1 - m) * r * lw1 + lb1;
    }
    cp_wait0();
    __syncthreads();

    u64 acc[6][4];
#pragma unroll
    for (int jj = 0; jj < 6; jj++) {
        u64 b = pk2(__ldg(&qkv_b[lane + 32 * jj]));
#pragma unroll
        for (int p = 0; p < 4; p++) acc[jj][p] = b;
    }
#pragma unroll 4
    for (int k2 = 0; k2 < 64; k2 += 2) {
        float2 wv[6];
#pragma unroll
        for (int jj = 0; jj < 6; jj++)
            wv[jj] = *(const float2*)&W[(lane + 32 * jj) * 70 + k2];
#pragma unroll
        for (int kk = 0; kk < 2; kk++) {
            int k = k2 + kk;
            ulonglong2 xa = *(const ulonglong2*)&xn[k * 68 + t0];
            ulonglong2 xb = *(const ulonglong2*)&xn[k * 68 + t0 + 4];
#pragma unroll
            for (int jj = 0; jj < 6; jj++) {
                u64 w = pk2(kk ? wv[jj].y : wv[jj].x);
                fma2(acc[jj][0], xa.x, w);
                fma2(acc[jj][1], xa.y, w);
                fma2(acc[jj][2], xb.x, w);
                fma2(acc[jj][3], xb.y, w);
            }
        }
    }
    float* qout = g_qkv + ((size_t)n * HW + hw0 + t0) * C3;
#pragma unroll
    for (int p = 0; p < 4; p++) {
#pragma unroll
        for (int jj = 0; jj < 6; jj++) {
            float2 v = up2(acc[jj][p]);
            if (jj < 2) { v.x *= 0.17677669529663687f; v.y *= 0.17677669529663687f; }
            qout[(size_t)(2 * p) * C3 + lane + 32 * jj]     = v.x;
            qout[(size_t)(2 * p + 1) * C3 + lane + 32 * jj] = v.y;
        }
    }
}

// ============================================================================
// K2: neighborhood attention (R12 proven version + float4 at[] broadcast AV).
// ============================================================================
__global__ __launch_bounds__(256, 3) void k_attn(const float* __restrict__ rpb)
{
    extern __shared__ float sm[];
    float* kx = sm;                  // [196][33]
    float* vx = kx + 196 * 33;       // [196][33]
    float* qx = vx + 196 * 33;       // [64][32]
    float* rp = qx + 64 * 32;        // [169]
    float* at = rp + 172;            // [8][52]

    const int tid = threadIdx.x, warp = tid >> 5, lane = tid & 31;
    const int b = blockIdx.x;
    const int nz = b >> 8, tile = b & 255;
    const int n = nz >> 1, z = nz & 1;
    const int h0 = (tile >> 4) << 3, w0 = (tile & 15) << 3;
    int r0 = h0 - 3; r0 = r0 < 0 ? 0 : (r0 > HT - 14 ? HT - 14 : r0);
    int c0 = w0 - 3; c0 = c0 < 0 ? 0 : (c0 > WD - 14 ? WD - 14 : c0);

    const float* qbase = g_qkv + (size_t)n * HW * C3;
    for (int rr = warp; rr < 196; rr += 8) {
        int pr = rr / 14, pc = rr - pr * 14;
        const float* p = qbase + (size_t)((r0 + pr) * WD + c0 + pc) * C3 + 64 + z * 32;
        cpa4(&kx[rr * 33 + lane], p + lane);
        cpa4(&vx[rr * 33 + lane], p + 64 + lane);
    }
    for (int qi = warp; qi < 64; qi += 8) {
        int qh = h0 + (qi >> 3), qw = w0 + (qi & 7);
        cpa4(&qx[qi * 32 + lane],
             qbase + (size_t)(qh * WD + qw) * C3 + z * 32 + lane);
    }
    if (tid < 169) cpa4(&rp[tid], &rpb[z * 169 + tid]);
    cp_commit();
    cp_wait0();
    __syncthreads();

    for (int j = 0; j < 8; j++) {
        const int qi = warp * 8 + j;
        const int qh = h0 + (qi >> 3), qw = w0 + (qi & 7);
        int sh = qh - 3; sh = sh < 0 ? 0 : (sh > HT - 7 ? HT - 7 : sh);
        int sw = qw - 3; sw = sw < 0 ? 0 : (sw > WD - 7 ? WD - 7 : sw);
        const int ph = sh - r0, pw = sw - c0;
        const int bh = qh - sh + 6, bw = qw - sw + 6;

        float s1, s2 = -1e30f;
        {
            int e = lane;
            int i = e / 7, jn = e - i * 7;
            const float* kr = &kx[((ph + i) * 14 + pw + jn) * 33];
            float s = rp[(bh - i) * 13 + (bw - jn)];
#pragma unroll
            for (int d4 = 0; d4 < 8; d4++) {
                float4 q4 = *(const float4*)&qx[qi * 32 + d4 * 4];
                s = fmaf(q4.x, kr[d4 * 4 + 0], s);
                s = fmaf(q4.y, kr[d4 * 4 + 1], s);
                s = fmaf(q4.z, kr[d4 * 4 + 2], s);
                s = fmaf(q4.w, kr[d4 * 4 + 3], s);
            }
            s1 = s;
        }
        if (lane < 17) {
            int e = lane + 32;
            int i = e / 7, jn = e - i * 7;
            const float* kr = &kx[((ph + i) * 14 + pw + jn) * 33];
            float s = rp[(bh - i) * 13 + (bw - jn)];
#pragma unroll
            for (int d4 = 0; d4 < 8; d4++) {
                float4 q4 = *(const float4*)&qx[qi * 32 + d4 * 4];
                s = fmaf(q4.x, kr[d4 * 4 + 0], s);
                s = fmaf(q4.y, kr[d4 * 4 + 1], s);
                s = fmaf(q4.z, kr[d4 * 4 + 2], s);
                s = fmaf(q4.w, kr[d4 * 4 + 3], s);
            }
            s2 = s;
        }
        float mx = warp_max(fmaxf(s1, s2));
        float p1 = __expf(s1 - mx);
        float p2 = (lane < 17) ? __expf(s2 - mx) : 0.0f;
        float inv = 1.0f / warp_sum(p1 + p2);
        at[warp * 52 + lane] = p1 * inv;
        if (lane < 17) at[warp * 52 + 32 + lane] = p2 * inv;
        __syncwarp();

        // AV: float4 broadcast reads of at[] (uniform address, conflict-free)
        const float* ab = &at[warp * 52];
        const float* vb = &vx[(ph * 14 + pw) * 33 + lane];
        float o = 0.0f;
#pragma unroll
        for (int e4 = 0; e4 < 48; e4 += 4) {
            float4 a4 = *(const float4*)&ab[e4];
            {int e=e4;   int i=e/7,jn=e-i*7; o = fmaf(a4.x, vb[(i*14+jn)*33], o);}
            {int e=e4+1; int i=e/7,jn=e-i*7; o = fmaf(a4.y, vb[(i*14+jn)*33], o);}
            {int e=e4+2; int i=e/7,jn=e-i*7; o = fmaf(a4.z, vb[(i*14+jn)*33], o);}
            {int e=e4+3; int i=e/7,jn=e-i*7; o = fmaf(a4.w, vb[(i*14+jn)*33], o);}
        }
        o = fmaf(ab[48], vb[(6 * 14 + 6) * 33], o);
        g_aout[(size_t)(n * HW + qh * WD + qw) * CH + z * 32 + lane] = o;
        __syncwarp();
    }
}

// ============================================================================
// K3 (fused): proj+residual+LN2+FC1(4 quarters)+GELU+FC2+residual+store
// WB stride 68 -> LDS.128 weight loads; vectorized output store. 4 CTAs/SM.
// ============================================================================
__global__ __launch_bounds__(256, 4) void k_mlp(
    const float* __restrict__ x, const float* __restrict__ proj_w,
    const float* __restrict__ proj_b, const float* __restrict__ fc1_w,
    const float* __restrict__ fc1_b, const float* __restrict__ fc2_b,
    const float* __restrict__ ln_w, const float* __restrict__ ln_b,
    float* __restrict__ out)
{
    extern __shared__ float sm[];
    float* XN = sm;                 // [64][68]
    float* AR = sm + 4352;          // [64][68]
    float* WB = sm + 8704;          // [64][68]
    float* BS = sm + 13056;         // fc1_b[256]

    const int tid = threadIdx.x, warp = tid >> 5, lane = tid & 31;
    const int n = blockIdx.x >> 8, hw0 = (blockIdx.x & 255) << 6;
    const int t0 = warp * 8;

    for (int idx = tid; idx < 64 * 64; idx += 256) {
        int o = idx >> 6, k = idx & 63;
        cpa4(&WB[o * 68 + k], &proj_w[idx]);
    }
    cp_commit();

    const float* ain = g_aout + ((size_t)n * HW + hw0) * CH;
    for (int idx = tid; idx < 64 * 64; idx += 256) {
        int t = idx >> 6, k = idx & 63;
        AR[k * 68 + t] = ain[(size_t)t * CH + k];
    }
    if (tid < C4) BS[tid] = fc1_b[tid];
    float x2c0[8], x2c1[8];
    {
        const float* xin = x + (size_t)n * CH * HW + hw0 + t0;
        float4 a = *(const float4*)&xin[(size_t)lane * HW];
        float4 b = *(const float4*)&xin[(size_t)lane * HW + 4];
        x2c0[0]=a.x; x2c0[1]=a.y; x2c0[2]=a.z; x2c0[3]=a.w;
        x2c0[4]=b.x; x2c0[5]=b.y; x2c0[6]=b.z; x2c0[7]=b.w;
        float4 c = *(const float4*)&xin[(size_t)(lane + 32) * HW];
        float4 d = *(const float4*)&xin[(size_t)(lane + 32) * HW + 4];
        x2c1[0]=c.x; x2c1[1]=c.y; x2c1[2]=c.z; x2c1[3]=c.w;
        x2c1[4]=d.x; x2c1[5]=d.y; x2c1[6]=d.z; x2c1[7]=d.w;
    }
    cp_wait0();
    __syncthreads();

    // ---- proj GEMM (float4 weight loads) ----
    {
        u64 a0[4], a1[4];
        u64 b0 = pk2(__ldg(&proj_b[lane])), b1 = pk2(__ldg(&proj_b[lane + 32]));
#pragma unroll
        for (int p = 0; p < 4; p++) { a0[p] = b0; a1[p] = b1; }
#pragma unroll 4
        for (int k4 = 0; k4 < 64; k4 += 4) {
            float4 wa = *(const float4*)&WB[lane * 68 + k4];
            float4 wb = *(const float4*)&WB[(lane + 32) * 68 + k4];
            float wav[4] = {wa.x, wa.y, wa.z, wa.w};
            float wbv[4] = {wb.x, wb.y, wb.z, wb.w};
#pragma unroll
            for (int kk = 0; kk < 4; kk++) {
                int k = k4 + kk;
                ulonglong2 xa = *(const ulonglong2*)&AR[k * 68 + t0];
                ulonglong2 xb = *(const ulonglong2*)&AR[k * 68 + t0 + 4];
                u64 w0 = pk2(wav[kk]);
                u64 w1 = pk2(wbv[kk]);
                fma2(a0[0], xa.x, w0); fma2(a0[1], xa.y, w0);
                fma2(a0[2], xb.x, w0); fma2(a0[3], xb.y, w0);
                fma2(a1[0], xa.x, w1); fma2(a1[1], xa.y, w1);
                fma2(a1[2], xb.x, w1); fma2(a1[3], xb.y, w1);
            }
        }
#pragma unroll
        for (int p = 0; p < 4; p++) {
            float2 v0 = up2(a0[p]), v1 = up2(a1[p]);
            x2c0[2 * p] += v0.x; x2c0[2 * p + 1] += v0.y;
            x2c1[2 * p] += v1.x; x2c1[2 * p + 1] += v1.y;
        }
    }
    __syncthreads();

    for (int idx = tid; idx < 64 * 64; idx += 256) {
        int o = idx >> 6, k = idx & 63;
        cpa4(&WB[o * 68 + k], &fc1_w[idx]);
    }
    cp_commit();

    // ---- LN2 -> XN ----
    {
        float lw0 = ln_w[lane], lb0 = ln_b[lane];
        float lw1 = ln_w[lane + 32], lb1 = ln_b[lane + 32];
#pragma unroll
        for (int t = 0; t < 8; t++) {
            float c0 = x2c0[t], c1 = x2c1[t];
            float s  = warp_sum(c0 + c1);
            float sq = warp_sum(c0 * c0 + c1 * c1);
            float m  = s * (1.0f / 64.0f);
            float r  = rsqrtf(sq * (1.0f / 64.0f) - m * m + 1e-5f);
            XN[lane * 68 + t0 + t]        = (c0 - m) * r * lw0 + lb0;
            XN[(lane + 32) * 68 + t0 + t] = (c1 - m) * r * lw1 + lb1;
        }
    }
    u64 f0[4], f1[4];
    {
        float bf0 = __ldg(&fc2_b[lane]), bf1 = __ldg(&fc2_b[lane + 32]);
#pragma unroll
        for (int p = 0; p < 4; p++) {
            f0[p] = pk2f(bf0 + x2c0[2 * p], bf0 + x2c0[2 * p + 1]);
            f1[p] = pk2f(bf1 + x2c1[2 * p], bf1 + x2c1[2 * p + 1]);
        }
    }
    cp_wait0();
    __syncthreads();

#pragma unroll 1
    for (int q = 0; q < 4; q++) {
        u64 acc[2][4];
#pragma unroll
        for (int jj = 0; jj < 2; jj++) {
            u64 bq = pk2(BS[64 * q + 32 * jj + lane]);
#pragma unroll
            for (int p = 0; p < 4; p++) acc[jj][p] = bq;
        }
#pragma unroll 4
        for (int k4 = 0; k4 < 64; k4 += 4) {
            float4 wa = *(const float4*)&WB[lane * 68 + k4];
            float4 wb = *(const float4*)&WB[(lane + 32) * 68 + k4];
            float wav[4] = {wa.x, wa.y, wa.z, wa.w};
            float wbv[4] = {wb.x, wb.y, wb.z, wb.w};
#pragma unroll
            for (int kk = 0; kk < 4; kk++) {
                int k = k4 + kk;
                ulonglong2 xa = *(const ulonglong2*)&XN[k * 68 + t0];
                ulonglong2 xb = *(const ulonglong2*)&XN[k * 68 + t0 + 4];
                u64 w0 = pk2(wav[kk]);
                u64 w1 = pk2(wbv[kk]);
                fma2(acc[0][0], xa.x, w0); fma2(acc[0][1], xa.y, w0);
                fma2(acc[0][2], xb.x, w0); fma2(acc[0][3], xb.y, w0);
                fma2(acc[1][0], xa.x, w1); fma2(acc[1][1], xa.y, w1);
                fma2(acc[1][2], xb.x, w1); fma2(acc[1][3], xb.y, w1);
            }
        }
#pragma unroll
        for (int jj = 0; jj < 2; jj++) {
#pragma unroll
            for (int p = 0; p < 4; p++) {
                float2 v = up2(acc[jj][p]);
                v.x = gelu_f(v.x);
                v.y = gelu_f(v.y);
                *(float2*)&AR[(lane + 32 * jj) * 68 + t0 + 2 * p] = v;
            }
        }
        __syncwarp();
        __syncthreads();
        if (q < 3) {
            const float* w1q = fc1_w + (size_t)(64 * (q + 1)) * 64;
            for (int idx = tid; idx < 64 * 64; idx += 256) {
                int o = idx >> 6, k = idx & 63;
                cpa4(&WB[o * 68 + k], &w1q[idx]);
            }
            cp_commit();
        }
        const float* w2r = &g_w2t[(size_t)(64 * q) * 64];
#pragma unroll 4
        for (int kk = 0; kk < 64; kk++) {
            ulonglong2 xa = *(const ulonglong2*)&AR[kk * 68 + t0];
            ulonglong2 xb = *(const ulonglong2*)&AR[kk * 68 + t0 + 4];
            u64 w0 = pk2(__ldg(&w2r[kk * 64 + lane]));
            u64 w1 = pk2(__ldg(&w2r[kk * 64 + lane + 32]));
            fma2(f0[0], xa.x, w0); fma2(f0[1], xa.y, w0);
            fma2(f0[2], xb.x, w0); fma2(f0[3], xb.y, w0);
            fma2(f1[0], xa.x, w1); fma2(f1[1], xa.y, w1);
            fma2(f1[2], xb.x, w1); fma2(f1[3], xb.y, w1);
        }
        if (q < 3) {
            cp_wait0();
            __syncthreads();
        }
    }
    __syncthreads();

#pragma unroll
    for (int p = 0; p < 4; p++) {
        float2 v0 = up2(f0[p]), v1 = up2(f1[p]);
        *(float2*)&AR[lane * 68 + t0 + 2 * p]        = v0;
        *(float2*)&AR[(lane + 32) * 68 + t0 + 2 * p] = v1;
    }
    __syncthreads();
    float* oo = out + (size_t)n * CH * HW + hw0;
    for (int idx = tid; idx < 64 * 16; idx += 256) {
        int c = idx >> 4, t4 = (idx & 15) * 4;
        float4 v = *(const float4*)&AR[c * 68 + t4];
        *(float4*)&oo[(size_t)c * HW + t4] = v;
    }
}

// ---------------------------------------------------------------------------
extern "C" void kernel_launch(void* const* d_in, const int* in_sizes, int n_in,
                              void* d_out, int out_size)
{
    const float* x      = (const float*)d_in[0];
    const float* qkv_w  = (const float*)d_in[1];
    const float* qkv_b  = (const float*)d_in[2];
    const float* proj_w = (const float*)d_in[3];
    const float* proj_b = (const float*)d_in[4];
    const float* rpb    = (const float*)d_in[5];
    const float* ln1_w  = (const float*)d_in[6];
    const float* ln1_b  = (const float*)d_in[7];
    const float* ln2_w  = (const float*)d_in[8];
    const float* ln2_b  = (const float*)d_in[9];
    const float* fc1_w  = (const float*)d_in[10];
    const float* fc1_b  = (const float*)d_in[11];
    const float* fc2_w  = (const float*)d_in[12];
    const float* fc2_b  = (const float*)d_in[13];
    float* out = (float*)d_out;

    const int smB = (4352 + C3 * 70) * 4;
    const int smC = (196 * 33 * 2 + 64 * 32 + 172 + 8 * 52) * 4;
    const int smM = (4352 + 4352 + 4352 + 256) * 4;

    cudaFuncSetAttribute(k_ln_qkv, cudaFuncAttributeMaxDynamicSharedMemorySize, smB);
    cudaFuncSetAttribute(k_attn,   cudaFuncAttributeMaxDynamicSharedMemorySize, smC);
    cudaFuncSetAttribute(k_mlp,    cudaFuncAttributeMaxDynamicSharedMemorySize, smM);

    k_ln_qkv<<<512, 256, smB>>>(x, qkv_w, qkv_b, ln1_w, ln1_b, fc2_w);
    k_attn<<<1024, 256, smC>>>(rpb);
    k_mlp<<<512, 256, smM>>>(x, proj_w, proj_b, fc1_w, fc1_b, fc2_b,
                             ln2_w, ln2_b, out);
}

// round 16
// speedup vs baseline: 1.0014x; 1.0014x over previous
#include <cuda_runtime.h>
#include <cuda_bf16.h>
#include <math.h>

#define NB   2
#define CH   64
#define HT   128
#define WD   128
#define HW   16384
#define C3   192
#define C4   256

typedef unsigned long long u64;

// ---------------- scratch (device globals; no allocation allowed) ----------
__device__ float g_qkv[NB * HW * C3];   // [token][192] (q pre-scaled)
__device__ float g_aout[NB * HW * CH];  // attention output, token-major
__device__ float g_w2t[C4 * CH];        // fc2_w transposed [256][64] (k-major)

__device__ __forceinline__ float warp_sum(float v) {
#pragma unroll
    for (int o = 16; o; o >>= 1) v += __shfl_xor_sync(0xffffffffu, v, o);
    return v;
}
__device__ __forceinline__ float warp_max(float v) {
#pragma unroll
    for (int o = 16; o; o >>= 1) v = fmaxf(v, __shfl_xor_sync(0xffffffffu, v, o));
    return v;
}
__device__ __forceinline__ u64 pk2(float v) {
    u64 r; asm("mov.b64 %0,{%1,%1};" : "=l"(r) : "f"(v)); return r;
}
__device__ __forceinline__ u64 pk2f(float a, float b) {
    u64 r; asm("mov.b64 %0,{%1,%2};" : "=l"(r) : "f"(a), "f"(b)); return r;
}
__device__ __forceinline__ void fma2(u64& d, u64 a, u64 b) {
    asm("fma.rn.f32x2 %0,%1,%2,%0;" : "+l"(d) : "l"(a), "l"(b));
}
__device__ __forceinline__ float2 up2(u64 v) {
    float2 f; asm("mov.b64 {%0,%1},%2;" : "=f"(f.x), "=f"(f.y) : "l"(v)); return f;
}
__device__ __forceinline__ void cpa4(void* s, const void* g) {
    unsigned sa = (unsigned)__cvta_generic_to_shared(s);
    asm volatile("cp.async.ca.shared.global [%0], [%1], 4;" :: "r"(sa), "l"(g));
}
__device__ __forceinline__ void cp_commit() { asm volatile("cp.async.commit_group;"); }
__device__ __forceinline__ void cp_wait0()  { asm volatile("cp.async.wait_group 0;"); }

// fast GELU (HW tanh.approx)
__device__ __forceinline__ float gelu_f(float x) {
    float t = x * x;
    float u = fmaf(t, 0.03567740814183373f, 0.7978845608028654f);
    float a = x * u;
    float th; asm("tanh.approx.f32 %0,%1;" : "=f"(th) : "f"(a));
    float hx = 0.5f * x;
    return fmaf(hx, th, hx);
}

// ============================================================================
// K1: [blocks 0-63: fc2 transpose] + LN1 + QKV GEMM in two output-half passes.
// W[96][70] single buffer re-staged -> smem 44.3KB, 4 CTAs/SM.
// ============================================================================
__global__ __launch_bounds__(256, 4) void k_ln_qkv(
    const float* __restrict__ x, const float* __restrict__ qkv_w,
    const float* __restrict__ qkv_b, const float* __restrict__ ln_w,
    const float* __restrict__ ln_b, const float* __restrict__ fc2_w)
{
    extern __shared__ float sm[];
    float* xn = sm;                 // [64][68] normalized, k-major
    float* W  = sm + 4352;          // [96][70] row-major, stride 70

    const int tid = threadIdx.x, warp = tid >> 5, lane = tid & 31;
    const int n = blockIdx.x >> 8;
    const int hw0 = (blockIdx.x & 255) << 6;
    const int t0 = warp * 8;
    const float* xin = x + (size_t)n * CH * HW + hw0 + t0;

    if (blockIdx.x < 64) {
        int i = blockIdx.x * 256 + tid;
        int c = i >> 8, k = i & 255;
        g_w2t[k * 64 + c] = fc2_w[i];
    }

    // stage W half 0 (outputs 0..95) — overlaps LN compute
    for (int idx = tid; idx < 96 * 64; idx += 256) {
        int o = idx >> 6, k = idx & 63;
        cpa4(&W[o * 70 + k], &qkv_w[idx]);
    }
    cp_commit();

    float xc0[8], xc1[8];
    {
        float4 a = *(const float4*)&xin[(size_t)lane * HW];
        float4 b = *(const float4*)&xin[(size_t)lane * HW + 4];
        xc0[0]=a.x; xc0[1]=a.y; xc0[2]=a.z; xc0[3]=a.w;
        xc0[4]=b.x; xc0[5]=b.y; xc0[6]=b.z; xc0[7]=b.w;
        float4 c = *(const float4*)&xin[(size_t)(lane + 32) * HW];
        float4 d = *(const float4*)&xin[(size_t)(lane + 32) * HW + 4];
        xc1[0]=c.x; xc1[1]=c.y; xc1[2]=c.z; xc1[3]=c.w;
        xc1[4]=d.x; xc1[5]=d.y; xc1[6]=d.z; xc1[7]=d.w;
    }
    float lw0 = ln_w[lane], lb0 = ln_b[lane];
    float lw1 = ln_w[lane + 32], lb1 = ln_b[lane + 32];
#pragma unroll
    for (int t = 0; t < 8; t++) {
        float c0 = xc0[t], c1 = xc1[t];
        float s  = warp_sum(c0 + c1);
        float sq = warp_sum(c0 * c0 + c1 * c1);
        float m  = s * (1.0f / 64.0f);
        float r  = rsqrtf(sq * (1.0f / 64.0f) - m * m + 1e-5f);
        xn[lane * 68 + t0 + t]        = (c0 - m) * r * lw0 + lb0;
        xn[(lane + 32) * 68 + t0 + t] = (c1 - m) * r * lw1 + lb1;
    }
    cp_wait0();
    __syncthreads();

    float* qout = g_qkv + ((size_t)n * HW + hw0 + t0) * C3;
#pragma unroll
    for (int h = 0; h < 2; h++) {
        u64 acc[3][4];
#pragma unroll
        for (int jj = 0; jj < 3; jj++) {
            u64 b = pk2(__ldg(&qkv_b[96 * h + lane + 32 * jj]));
#pragma unroll
            for (int p = 0; p < 4; p++) acc[jj][p] = b;
        }
#pragma unroll 4
        for (int k2 = 0; k2 < 64; k2 += 2) {
            float2 wv[3];
#pragma unroll
            for (int jj = 0; jj < 3; jj++)
                wv[jj] = *(const float2*)&W[(lane + 32 * jj) * 70 + k2];
#pragma unroll
            for (int kk = 0; kk < 2; kk++) {
                int k = k2 + kk;
                ulonglong2 xa = *(const ulonglong2*)&xn[k * 68 + t0];
                ulonglong2 xb = *(const ulonglong2*)&xn[k * 68 + t0 + 4];
#pragma unroll
                for (int jj = 0; jj < 3; jj++) {
                    u64 w = pk2(kk ? wv[jj].y : wv[jj].x);
                    fma2(acc[jj][0], xa.x, w);
                    fma2(acc[jj][1], xa.y, w);
                    fma2(acc[jj][2], xb.x, w);
                    fma2(acc[jj][3], xb.y, w);
                }
            }
        }
#pragma unroll
        for (int p = 0; p < 4; p++) {
#pragma unroll
            for (int jj = 0; jj < 3; jj++) {
                float2 v = up2(acc[jj][p]);
                if (h == 0 && jj < 2) {
                    v.x *= 0.17677669529663687f; v.y *= 0.17677669529663687f;
                }
                int o = 96 * h + lane + 32 * jj;
                qout[(size_t)(2 * p) * C3 + o]     = v.x;
                qout[(size_t)(2 * p + 1) * C3 + o] = v.y;
            }
        }
        if (h == 0) {
            __syncthreads();     // all warps done reading W half 0
            const float* w1 = qkv_w + 96 * 64;
            for (int idx = tid; idx < 96 * 64; idx += 256) {
                int o = idx >> 6, k = idx & 63;
                cpa4(&W[o * 70 + k], &w1[idx]);
            }
            cp_commit();
            cp_wait0();
            __syncthreads();
        }
    }
}

// ============================================================================
// K2: neighborhood attention (verbatim R12 — proven best).
// ============================================================================
__global__ __launch_bounds__(256, 3) void k_attn(const float* __restrict__ rpb)
{
    extern __shared__ float sm[];
    float* kx = sm;                  // [196][33]
    float* vx = kx + 196 * 33;       // [196][33]
    float* qx = vx + 196 * 33;       // [64][32]
    float* rp = qx + 64 * 32;        // [169]
    float* at = rp + 172;            // [8][52]

    const int tid = threadIdx.x, warp = tid >> 5, lane = tid & 31;
    const int b = blockIdx.x;
    const int nz = b >> 8, tile = b & 255;
    const int n = nz >> 1, z = nz & 1;
    const int h0 = (tile >> 4) << 3, w0 = (tile & 15) << 3;
    int r0 = h0 - 3; r0 = r0 < 0 ? 0 : (r0 > HT - 14 ? HT - 14 : r0);
    int c0 = w0 - 3; c0 = c0 < 0 ? 0 : (c0 > WD - 14 ? WD - 14 : c0);

    const float* qbase = g_qkv + (size_t)n * HW * C3;
    for (int rr = warp; rr < 196; rr += 8) {
        int pr = rr / 14, pc = rr - pr * 14;
        const float* p = qbase + (size_t)((r0 + pr) * WD + c0 + pc) * C3 + 64 + z * 32;
        cpa4(&kx[rr * 33 + lane], p + lane);
        cpa4(&vx[rr * 33 + lane], p + 64 + lane);
    }
    for (int qi = warp; qi < 64; qi += 8) {
        int qh = h0 + (qi >> 3), qw = w0 + (qi & 7);
        cpa4(&qx[qi * 32 + lane],
             qbase + (size_t)(qh * WD + qw) * C3 + z * 32 + lane);
    }
    if (tid < 169) cpa4(&rp[tid], &rpb[z * 169 + tid]);
    cp_commit();
    cp_wait0();
    __syncthreads();

    for (int j = 0; j < 8; j++) {
        const int qi = warp * 8 + j;
        const int qh = h0 + (qi >> 3), qw = w0 + (qi & 7);
        int sh = qh - 3; sh = sh < 0 ? 0 : (sh > HT - 7 ? HT - 7 : sh);
        int sw = qw - 3; sw = sw < 0 ? 0 : (sw > WD - 7 ? WD - 7 : sw);
        const int ph = sh - r0, pw = sw - c0;
        const int bh = qh - sh + 6, bw = qw - sw + 6;

        float s1, s2 = -1e30f;
        {
            int e = lane;
            int i = e / 7, jn = e - i * 7;
            const float* kr = &kx[((ph + i) * 14 + pw + jn) * 33];
            float s = rp[(bh - i) * 13 + (bw - jn)];
#pragma unroll
            for (int d4 = 0; d4 < 8; d4++) {
                float4 q4 = *(const float4*)&qx[qi * 32 + d4 * 4];
                s = fmaf(q4.x, kr[d4 * 4 + 0], s);
                s = fmaf(q4.y, kr[d4 * 4 + 1], s);
                s = fmaf(q4.z, kr[d4 * 4 + 2], s);
                s = fmaf(q4.w, kr[d4 * 4 + 3], s);
            }
            s1 = s;
        }
        if (lane < 17) {
            int e = lane + 32;
            int i = e / 7, jn = e - i * 7;
            const float* kr = &kx[((ph + i) * 14 + pw + jn) * 33];
            float s = rp[(bh - i) * 13 + (bw - jn)];
#pragma unroll
            for (int d4 = 0; d4 < 8; d4++) {
                float4 q4 = *(const float4*)&qx[qi * 32 + d4 * 4];
                s = fmaf(q4.x, kr[d4 * 4 + 0], s);
                s = fmaf(q4.y, kr[d4 * 4 + 1], s);
                s = fmaf(q4.z, kr[d4 * 4 + 2], s);
                s = fmaf(q4.w, kr[d4 * 4 + 3], s);
            }
            s2 = s;
        }
        float mx = warp_max(fmaxf(s1, s2));
        float p1 = __expf(s1 - mx);
        float p2 = (lane < 17) ? __expf(s2 - mx) : 0.0f;
        float inv = 1.0f / warp_sum(p1 + p2);
        at[warp * 52 + lane] = p1 * inv;
        if (lane < 17) at[warp * 52 + 32 + lane] = p2 * inv;
        __syncwarp();

        float o = 0.0f;
#pragma unroll
        for (int e = 0; e < 49; e++) {
            int i = e / 7, jn = e - i * 7;
            o = fmaf(at[warp * 52 + e], vx[((ph + i) * 14 + pw + jn) * 33 + lane], o);
        }
        g_aout[(size_t)(n * HW + qh * WD + qw) * CH + z * 32 + lane] = o;
        __syncwarp();
    }
}

// ============================================================================
// K3 (fused): proj+residual+LN2+FC1(4 quarters)+GELU+FC2+residual+store
// (verbatim R12 — proven best). 4 CTAs/SM.
// ============================================================================
__global__ __launch_bounds__(256, 4) void k_mlp(
    const float* __restrict__ x, const float* __restrict__ proj_w,
    const float* __restrict__ proj_b, const float* __restrict__ fc1_w,
    const float* __restrict__ fc1_b, const float* __restrict__ fc2_b,
    const float* __restrict__ ln_w, const float* __restrict__ ln_b,
    float* __restrict__ out)
{
    extern __shared__ float sm[];
    float* XN = sm;                 // [64][68]
    float* AR = sm + 4352;          // [64][68]
    float* WB = sm + 8704;          // [64][68]
    float* BS = sm + 13056;         // fc1_b[256]

    const int tid = threadIdx.x, warp = tid >> 5, lane = tid & 31;
    const int n = blockIdx.x >> 8, hw0 = (blockIdx.x & 255) << 6;
    const int t0 = warp * 8;

    for (int idx = tid; idx < 64 * 64; idx += 256) {
        int o = idx >> 6, k = idx & 63;
        cpa4(&WB[o * 68 + k], &proj_w[idx]);
    }
    cp_commit();

    const float* ain = g_aout + ((size_t)n * HW + hw0) * CH;
    for (int idx = tid; idx < 64 * 64; idx += 256) {
        int t = idx >> 6, k = idx & 63;
        AR[k * 68 + t] = ain[(size_t)t * CH + k];
    }
    if (tid < C4) BS[tid] = fc1_b[tid];
    float x2c0[8], x2c1[8];
    {
        const float* xin = x + (size_t)n * CH * HW + hw0 + t0;
        float4 a = *(const float4*)&xin[(size_t)lane * HW];
        float4 b = *(const float4*)&xin[(size_t)lane * HW + 4];
        x2c0[0]=a.x; x2c0[1]=a.y; x2c0[2]=a.z; x2c0[3]=a.w;
        x2c0[4]=b.x; x2c0[5]=b.y; x2c0[6]=b.z; x2c0[7]=b.w;
        float4 c = *(const float4*)&xin[(size_t)(lane + 32) * HW];
        float4 d = *(const float4*)&xin[(size_t)(lane + 32) * HW + 4];
        x2c1[0]=c.x; x2c1[1]=c.y; x2c1[2]=c.z; x2c1[3]=c.w;
        x2c1[4]=d.x; x2c1[5]=d.y; x2c1[6]=d.z; x2c1[7]=d.w;
    }
    cp_wait0();
    __syncthreads();

    // ---- proj GEMM (float4 weight loads) ----
    {
        u64 a0[4], a1[4];
        u64 b0 = pk2(__ldg(&proj_b[lane])), b1 = pk2(__ldg(&proj_b[lane + 32]));
#pragma unroll
        for (int p = 0; p < 4; p++) { a0[p] = b0; a1[p] = b1; }
#pragma unroll 4
        for (int k4 = 0; k4 < 64; k4 += 4) {
            float4 wa = *(const float4*)&WB[lane * 68 + k4];
            float4 wb = *(const float4*)&WB[(lane + 32) * 68 + k4];
            float wav[4] = {wa.x, wa.y, wa.z, wa.w};
            float wbv[4] = {wb.x, wb.y, wb.z, wb.w};
#pragma unroll
            for (int kk = 0; kk < 4; kk++) {
                int k = k4 + kk;
                ulonglong2 xa = *(const ulonglong2*)&AR[k * 68 + t0];
                ulonglong2 xb = *(const ulonglong2*)&AR[k * 68 + t0 + 4];
                u64 w0 = pk2(wav[kk]);
                u64 w1 = pk2(wbv[kk]);
                fma2(a0[0], xa.x, w0); fma2(a0[1], xa.y, w0);
                fma2(a0[2], xb.x, w0); fma2(a0[3], xb.y, w0);
                fma2(a1[0], xa.x, w1); fma2(a1[1], xa.y, w1);
                fma2(a1[2], xb.x, w1); fma2(a1[3], xb.y, w1);
            }
        }
#pragma unroll
        for (int p = 0; p < 4; p++) {
            float2 v0 = up2(a0[p]), v1 = up2(a1[p]);
            x2c0[2 * p] += v0.x; x2c0[2 * p + 1] += v0.y;
            x2c1[2 * p] += v1.x; x2c1[2 * p + 1] += v1.y;
        }
    }
    __syncthreads();

    for (int idx = tid; idx < 64 * 64; idx += 256) {
        int o = idx >> 6, k = idx & 63;
        cpa4(&WB[o * 68 + k], &fc1_w[idx]);
    }
    cp_commit();

    // ---- LN2 -> XN ----
    {
        float lw0 = ln_w[lane], lb0 = ln_b[lane];
        float lw1 = ln_w[lane + 32], lb1 = ln_b[lane + 32];
#pragma unroll
        for (int t = 0; t < 8; t++) {
            float c0 = x2c0[t], c1 = x2c1[t];
            float s  = warp_sum(c0 + c1);
            float sq = warp_sum(c0 * c0 + c1 * c1);
            float m  = s * (1.0f / 64.0f);
            float r  = rsqrtf(sq * (1.0f / 64.0f) - m * m + 1e-5f);
            XN[lane * 68 + t0 + t]        = (c0 - m) * r * lw0 + lb0;
            XN[(lane + 32) * 68 + t0 + t] = (c1 - m) * r * lw1 + lb1;
        }
    }
    u64 f0[4], f1[4];
    {
        float bf0 = __ldg(&fc2_b[lane]), bf1 = __ldg(&fc2_b[lane + 32]);
#pragma unroll
        for (int p = 0; p < 4; p++) {
            f0[p] = pk2f(bf0 + x2c0[2 * p], bf0 + x2c0[2 * p + 1]);
            f1[p] = pk2f(bf1 + x2c1[2 * p], bf1 + x2c1[2 * p + 1]);
        }
    }
    cp_wait0();
    __syncthreads();

#pragma unroll 1
    for (int q = 0; q < 4; q++) {
        u64 acc[2][4];
#pragma unroll
        for (int jj = 0; jj < 2; jj++) {
            u64 bq = pk2(BS[64 * q + 32 * jj + lane]);
#pragma unroll
            for (int p = 0; p < 4; p++) acc[jj][p] = bq;
        }
#pragma unroll 4
        for (int k4 = 0; k4 < 64; k4 += 4) {
            float4 wa = *(const float4*)&WB[lane * 68 + k4];
            float4 wb = *(const float4*)&WB[(lane + 32) * 68 + k4];
            float wav[4] = {wa.x, wa.y, wa.z, wa.w};
            float wbv[4] = {wb.x, wb.y, wb.z, wb.w};
#pragma unroll
            for (int kk = 0; kk < 4; kk++) {
                int k = k4 + kk;
                ulonglong2 xa = *(const ulonglong2*)&XN[k * 68 + t0];
                ulonglong2 xb = *(const ulonglong2*)&XN[k * 68 + t0 + 4];
                u64 w0 = pk2(wav[kk]);
                u64 w1 = pk2(wbv[kk]);
                fma2(acc[0][0], xa.x, w0); fma2(acc[0][1], xa.y, w0);
                fma2(acc[0][2], xb.x, w0); fma2(acc[0][3], xb.y, w0);
                fma2(acc[1][0], xa.x, w1); fma2(acc[1][1], xa.y, w1);
                fma2(acc[1][2], xb.x, w1); fma2(acc[1][3], xb.y, w1);
            }
        }
#pragma unroll
        for (int jj = 0; jj < 2; jj++) {
#pragma unroll
            for (int p = 0; p < 4; p++) {
                float2 v = up2(acc[jj][p]);
                v.x = gelu_f(v.x);
                v.y = gelu_f(v.y);
                *(float2*)&AR[(lane + 32 * jj) * 68 + t0 + 2 * p] = v;
            }
        }
        __syncwarp();
        __syncthreads();
        if (q < 3) {
            const float* w1q = fc1_w + (size_t)(64 * (q + 1)) * 64;
            for (int idx = tid; idx < 64 * 64; idx += 256) {
                int o = idx >> 6, k = idx & 63;
                cpa4(&WB[o * 68 + k], &w1q[idx]);
            }
            cp_commit();
        }
        const float* w2r = &g_w2t[(size_t)(64 * q) * 64];
#pragma unroll 4
        for (int kk = 0; kk < 64; kk++) {
            ulonglong2 xa = *(const ulonglong2*)&AR[kk * 68 + t0];
            ulonglong2 xb = *(const ulonglong2*)&AR[kk * 68 + t0 + 4];
            u64 w0 = pk2(__ldg(&w2r[kk * 64 + lane]));
            u64 w1 = pk2(__ldg(&w2r[kk * 64 + lane + 32]));
            fma2(f0[0], xa.x, w0); fma2(f0[1], xa.y, w0);
            fma2(f0[2], xb.x, w0); fma2(f0[3], xb.y, w0);
            fma2(f1[0], xa.x, w1); fma2(f1[1], xa.y, w1);
            fma2(f1[2], xb.x, w1); fma2(f1[3], xb.y, w1);
        }
        if (q < 3) {
            cp_wait0();
            __syncthreads();
        }
    }
    __syncthreads();

#pragma unroll
    for (int p = 0; p < 4; p++) {
        float2 v0 = up2(f0[p]), v1 = up2(f1[p]);
        *(float2*)&AR[lane * 68 + t0 + 2 * p]        = v0;
        *(float2*)&AR[(lane + 32) * 68 + t0 + 2 * p] = v1;
    }
    __syncthreads();
    float* oo = out + (size_t)n * CH * HW + hw0;
    for (int idx = tid; idx < 64 * 64; idx += 256) {
        int c = idx >> 6, t = idx & 63;
        oo[(size_t)c * HW + t] = AR[c * 68 + t];
    }
}

// ---------------------------------------------------------------------------
extern "C" void kernel_launch(void* const* d_in, const int* in_sizes, int n_in,
                              void* d_out, int out_size)
{
    const float* x      = (const float*)d_in[0];
    const float* qkv_w  = (const float*)d_in[1];
    const float* qkv_b  = (const float*)d_in[2];
    const float* proj_w = (const float*)d_in[3];
    const float* proj_b = (const float*)d_in[4];
    const float* rpb    = (const float*)d_in[5];
    const float* ln1_w  = (const float*)d_in[6];
    const float* ln1_b  = (const float*)d_in[7];
    const float* ln2_w  = (const float*)d_in[8];
    const float* ln2_b  = (const float*)d_in[9];
    const float* fc1_w  = (const float*)d_in[10];
    const float* fc1_b  = (const float*)d_in[11];
    const float* fc2_w  = (const float*)d_in[12];
    const float* fc2_b  = (const float*)d_in[13];
    float* out = (float*)d_out;

    const int smB = (4352 + 96 * 70) * 4;
    const int smC = (196 * 33 * 2 + 64 * 32 + 172 + 8 * 52) * 4;
    const int smM = (4352 + 4352 + 4352 + 256) * 4;

    cudaFuncSetAttribute(k_ln_qkv, cudaFuncAttributeMaxDynamicSharedMemorySize, smB);
    cudaFuncSetAttribute(k_attn,   cudaFuncAttributeMaxDynamicSharedMemorySize, smC);
    cudaFuncSetAttribute(k_mlp,    cudaFuncAttributeMaxDynamicSharedMemorySize, smM);

    k_ln_qkv<<<512, 256, smB>>>(x, qkv_w, qkv_b, ln1_w, ln1_b, fc2_w);
    k_attn<<<1024, 256, smC>>>(rpb);
    k_mlp<<<512, 256, smM>>>(x, proj_w, proj_b, fc1_w, fc1_b, fc2_b,
                             ln2_w, ln2_b, out);
}

// round 17
// speedup vs baseline: 1.0138x; 1.0124x over previous
#include <cuda_runtime.h>
#include <cuda_bf16.h>
#include <math.h>

#define NB   2
#define CH   64
#define HT   128
#define WD   128
#define HW   16384
#define C3   192
#define C4   256

typedef unsigned long long u64;

// ---------------- scratch (device globals; no allocation allowed) ----------
__device__ float g_qkv[NB * HW * C3];   // [token][192] (q pre-scaled)
__device__ float g_aout[NB * HW * CH];  // attention output, token-major
__device__ float g_w2t[C4 * CH];        // fc2_w transposed [256][64] (k-major)

__device__ __forceinline__ float warp_sum(float v) {
#pragma unroll
    for (int o = 16; o; o >>= 1) v += __shfl_xor_sync(0xffffffffu, v, o);
    return v;
}
__device__ __forceinline__ float warp_max(float v) {
#pragma unroll
    for (int o = 16; o; o >>= 1) v = fmaxf(v, __shfl_xor_sync(0xffffffffu, v, o));
    return v;
}
__device__ __forceinline__ u64 pk2(float v) {
    u64 r; asm("mov.b64 %0,{%1,%1};" : "=l"(r) : "f"(v)); return r;
}
__device__ __forceinline__ u64 pk2f(float a, float b) {
    u64 r; asm("mov.b64 %0,{%1,%2};" : "=l"(r) : "f"(a), "f"(b)); return r;
}
__device__ __forceinline__ void fma2(u64& d, u64 a, u64 b) {
    asm("fma.rn.f32x2 %0,%1,%2,%0;" : "+l"(d) : "l"(a), "l"(b));
}
__device__ __forceinline__ float2 up2(u64 v) {
    float2 f; asm("mov.b64 {%0,%1},%2;" : "=f"(f.x), "=f"(f.y) : "l"(v)); return f;
}
__device__ __forceinline__ void cpa4(void* s, const void* g) {
    unsigned sa = (unsigned)__cvta_generic_to_shared(s);
    asm volatile("cp.async.ca.shared.global [%0], [%1], 4;" :: "r"(sa), "l"(g));
}
__device__ __forceinline__ void cp_commit() { asm volatile("cp.async.commit_group;"); }
__device__ __forceinline__ void cp_wait0()  { asm volatile("cp.async.wait_group 0;"); }

// fast GELU (HW tanh.approx)
__device__ __forceinline__ float gelu_f(float x) {
    float t = x * x;
    float u = fmaf(t, 0.03567740814183373f, 0.7978845608028654f);
    float a = x * u;
    float th; asm("tanh.approx.f32 %0,%1;" : "=f"(th) : "f"(a));
    float hx = 0.5f * x;
    return fmaf(hx, th, hx);
}

// ============================================================================
// K1: [blocks 0-63: fc2 transpose] + LN1 + QKV GEMM (weights [o][70], LDS.64).
// (verbatim R12)
// ============================================================================
__global__ __launch_bounds__(256, 3) void k_ln_qkv(
    const float* __restrict__ x, const float* __restrict__ qkv_w,
    const float* __restrict__ qkv_b, const float* __restrict__ ln_w,
    const float* __restrict__ ln_b, const float* __restrict__ fc2_w)
{
    extern __shared__ float sm[];
    float* xn = sm;                 // [64][68] normalized, k-major
    float* W  = sm + 4352;          // [192][70] row-major, stride 70

    const int tid = threadIdx.x, warp = tid >> 5, lane = tid & 31;
    const int n = blockIdx.x >> 8;
    const int hw0 = (blockIdx.x & 255) << 6;
    const int t0 = warp * 8;
    const float* xin = x + (size_t)n * CH * HW + hw0 + t0;

    if (blockIdx.x < 64) {
        int i = blockIdx.x * 256 + tid;
        int c = i >> 8, k = i & 255;
        g_w2t[k * 64 + c] = fc2_w[i];
    }

    for (int idx = tid; idx < C3 * 64; idx += 256) {
        int o = idx >> 6, k = idx & 63;
        cpa4(&W[o * 70 + k], &qkv_w[idx]);
    }
    cp_commit();

    float xc0[8], xc1[8];
    {
        float4 a = *(const float4*)&xin[(size_t)lane * HW];
        float4 b = *(const float4*)&xin[(size_t)lane * HW + 4];
        xc0[0]=a.x; xc0[1]=a.y; xc0[2]=a.z; xc0[3]=a.w;
        xc0[4]=b.x; xc0[5]=b.y; xc0[6]=b.z; xc0[7]=b.w;
        float4 c = *(const float4*)&xin[(size_t)(lane + 32) * HW];
        float4 d = *(const float4*)&xin[(size_t)(lane + 32) * HW + 4];
        xc1[0]=c.x; xc1[1]=c.y; xc1[2]=c.z; xc1[3]=c.w;
        xc1[4]=d.x; xc1[5]=d.y; xc1[6]=d.z; xc1[7]=d.w;
    }
    float lw0 = ln_w[lane], lb0 = ln_b[lane];
    float lw1 = ln_w[lane + 32], lb1 = ln_b[lane + 32];
#pragma unroll
    for (int t = 0; t < 8; t++) {
        float c0 = xc0[t], c1 = xc1[t];
        float s  = warp_sum(c0 + c1);
        float sq = warp_sum(c0 * c0 + c1 * c1);
        float m  = s * (1.0f / 64.0f);
        float r  = rsqrtf(sq * (1.0f / 64.0f) - m * m + 1e-5f);
        xn[lane * 68 + t0 + t]        = (c0 - m) * r * lw0 + lb0;
        xn[(lane + 32) * 68 + t0 + t] = (c1 - m) * r * lw1 + lb1;
    }
    cp_wait0();
    __syncthreads();

    u64 acc[6][4];
#pragma unroll
    for (int jj = 0; jj < 6; jj++) {
        u64 b = pk2(__ldg(&qkv_b[lane + 32 * jj]));
#pragma unroll
        for (int p = 0; p < 4; p++) acc[jj][p] = b;
    }
#pragma unroll 4
    for (int k2 = 0; k2 < 64; k2 += 2) {
        float2 wv[6];
#pragma unroll
        for (int jj = 0; jj < 6; jj++)
            wv[jj] = *(const float2*)&W[(lane + 32 * jj) * 70 + k2];
#pragma unroll
        for (int kk = 0; kk < 2; kk++) {
            int k = k2 + kk;
            ulonglong2 xa = *(const ulonglong2*)&xn[k * 68 + t0];
            ulonglong2 xb = *(const ulonglong2*)&xn[k * 68 + t0 + 4];
#pragma unroll
            for (int jj = 0; jj < 6; jj++) {
                u64 w = pk2(kk ? wv[jj].y : wv[jj].x);
                fma2(acc[jj][0], xa.x, w);
                fma2(acc[jj][1], xa.y, w);
                fma2(acc[jj][2], xb.x, w);
                fma2(acc[jj][3], xb.y, w);
            }
        }
    }
    float* qout = g_qkv + ((size_t)n * HW + hw0 + t0) * C3;
#pragma unroll
    for (int p = 0; p < 4; p++) {
#pragma unroll
        for (int jj = 0; jj < 6; jj++) {
            float2 v = up2(acc[jj][p]);
            if (jj < 2) { v.x *= 0.17677669529663687f; v.y *= 0.17677669529663687f; }
            qout[(size_t)(2 * p) * C3 + lane + 32 * jj]     = v.x;
            qout[(size_t)(2 * p + 1) * C3 + lane + 32 * jj] = v.y;
        }
    }
}

// ============================================================================
// K2: neighborhood attention (R12 + lane-constant index hoist, ALU-only).
// ============================================================================
__global__ __launch_bounds__(256, 3) void k_attn(const float* __restrict__ rpb)
{
    extern __shared__ float sm[];
    float* kx = sm;                  // [196][33]
    float* vx = kx + 196 * 33;       // [196][33]
    float* qx = vx + 196 * 33;       // [64][32]
    float* rp = qx + 64 * 32;        // [169]
    float* at = rp + 172;            // [8][52]

    const int tid = threadIdx.x, warp = tid >> 5, lane = tid & 31;
    const int b = blockIdx.x;
    const int nz = b >> 8, tile = b & 255;
    const int n = nz >> 1, z = nz & 1;
    const int h0 = (tile >> 4) << 3, w0 = (tile & 15) << 3;
    int r0 = h0 - 3; r0 = r0 < 0 ? 0 : (r0 > HT - 14 ? HT - 14 : r0);
    int c0 = w0 - 3; c0 = c0 < 0 ? 0 : (c0 > WD - 14 ? WD - 14 : c0);

    const float* qbase = g_qkv + (size_t)n * HW * C3;
    for (int rr = warp; rr < 196; rr += 8) {
        int pr = rr / 14, pc = rr - pr * 14;
        const float* p = qbase + (size_t)((r0 + pr) * WD + c0 + pc) * C3 + 64 + z * 32;
        cpa4(&kx[rr * 33 + lane], p + lane);
        cpa4(&vx[rr * 33 + lane], p + 64 + lane);
    }
    for (int qi = warp; qi < 64; qi += 8) {
        int qh = h0 + (qi >> 3), qw = w0 + (qi & 7);
        cpa4(&qx[qi * 32 + lane],
             qbase + (size_t)(qh * WD + qw) * C3 + z * 32 + lane);
    }
    if (tid < 169) cpa4(&rp[tid], &rpb[z * 169 + tid]);
    cp_commit();
    cp_wait0();
    __syncthreads();

    // lane-constant neighbor indices, hoisted out of the query loop
    const int i1 = lane / 7, j1 = lane - i1 * 7;
    const int e2 = lane + 32;
    const int i2 = e2 / 7, j2 = e2 - i2 * 7;
    const bool valid = lane < 17;

    for (int j = 0; j < 8; j++) {
        const int qi = warp * 8 + j;
        const int qh = h0 + (qi >> 3), qw = w0 + (qi & 7);
        int sh = qh - 3; sh = sh < 0 ? 0 : (sh > HT - 7 ? HT - 7 : sh);
        int sw = qw - 3; sw = sw < 0 ? 0 : (sw > WD - 7 ? WD - 7 : sw);
        const int ph = sh - r0, pw = sw - c0;
        const int bh = qh - sh + 6, bw = qw - sw + 6;

        float s1, s2 = -1e30f;
        {
            const float* kr = &kx[((ph + i1) * 14 + pw + j1) * 33];
            float s = rp[(bh - i1) * 13 + (bw - j1)];
#pragma unroll
            for (int d4 = 0; d4 < 8; d4++) {
                float4 q4 = *(const float4*)&qx[qi * 32 + d4 * 4];
                s = fmaf(q4.x, kr[d4 * 4 + 0], s);
                s = fmaf(q4.y, kr[d4 * 4 + 1], s);
                s = fmaf(q4.z, kr[d4 * 4 + 2], s);
                s = fmaf(q4.w, kr[d4 * 4 + 3], s);
            }
            s1 = s;
        }
        if (valid) {
            const float* kr = &kx[((ph + i2) * 14 + pw + j2) * 33];
            float s = rp[(bh - i2) * 13 + (bw - j2)];
#pragma unroll
            for (int d4 = 0; d4 < 8; d4++) {
                float4 q4 = *(const float4*)&qx[qi * 32 + d4 * 4];
                s = fmaf(q4.x, kr[d4 * 4 + 0], s);
                s = fmaf(q4.y, kr[d4 * 4 + 1], s);
                s = fmaf(q4.z, kr[d4 * 4 + 2], s);
                s = fmaf(q4.w, kr[d4 * 4 + 3], s);
            }
            s2 = s;
        }
        float mx = warp_max(fmaxf(s1, s2));
        float p1 = __expf(s1 - mx);
        float p2 = valid ? __expf(s2 - mx) : 0.0f;
        float inv = 1.0f / warp_sum(p1 + p2);
        at[warp * 52 + lane] = p1 * inv;
        if (valid) at[warp * 52 + 32 + lane] = p2 * inv;
        __syncwarp();

        float o = 0.0f;
#pragma unroll
        for (int e = 0; e < 49; e++) {
            int i = e / 7, jn = e - i * 7;
            o = fmaf(at[warp * 52 + e], vx[((ph + i) * 14 + pw + jn) * 33 + lane], o);
        }
        g_aout[(size_t)(n * HW + qh * WD + qw) * CH + z * 32 + lane] = o;
        __syncwarp();
    }
}

// ============================================================================
// K3 (fused): proj+residual+LN2+FC1(4 quarters)+GELU+FC2+residual+store
// (verbatim R12). 4 CTAs/SM.
// ============================================================================
__global__ __launch_bounds__(256, 4) void k_mlp(
    const float* __restrict__ x, const float* __restrict__ proj_w,
    const float* __restrict__ proj_b, const float* __restrict__ fc1_w,
    const float* __restrict__ fc1_b, const float* __restrict__ fc2_b,
    const float* __restrict__ ln_w, const float* __restrict__ ln_b,
    float* __restrict__ out)
{
    extern __shared__ float sm[];
    float* XN = sm;                 // [64][68]
    float* AR = sm + 4352;          // [64][68]
    float* WB = sm + 8704;          // [64][68]
    float* BS = sm + 13056;         // fc1_b[256]

    const int tid = threadIdx.x, warp = tid >> 5, lane = tid & 31;
    const int n = blockIdx.x >> 8, hw0 = (blockIdx.x & 255) << 6;
    const int t0 = warp * 8;

    for (int idx = tid; idx < 64 * 64; idx += 256) {
        int o = idx >> 6, k = idx & 63;
        cpa4(&WB[o * 68 + k], &proj_w[idx]);
    }
    cp_commit();

    const float* ain = g_aout + ((size_t)n * HW + hw0) * CH;
    for (int idx = tid; idx < 64 * 64; idx += 256) {
        int t = idx >> 6, k = idx & 63;
        AR[k * 68 + t] = ain[(size_t)t * CH + k];
    }
    if (tid < C4) BS[tid] = fc1_b[tid];
    float x2c0[8], x2c1[8];
    {
        const float* xin = x + (size_t)n * CH * HW + hw0 + t0;
        float4 a = *(const float4*)&xin[(size_t)lane * HW];
        float4 b = *(const float4*)&xin[(size_t)lane * HW + 4];
        x2c0[0]=a.x; x2c0[1]=a.y; x2c0[2]=a.z; x2c0[3]=a.w;
        x2c0[4]=b.x; x2c0[5]=b.y; x2c0[6]=b.z; x2c0[7]=b.w;
        float4 c = *(const float4*)&xin[(size_t)(lane + 32) * HW];
        float4 d = *(const float4*)&xin[(size_t)(lane + 32) * HW + 4];
        x2c1[0]=c.x; x2c1[1]=c.y; x2c1[2]=c.z; x2c1[3]=c.w;
        x2c1[4]=d.x; x2c1[5]=d.y; x2c1[6]=d.z; x2c1[7]=d.w;
    }
    cp_wait0();
    __syncthreads();

    // ---- proj GEMM (float4 weight loads) ----
    {
        u64 a0[4], a1[4];
        u64 b0 = pk2(__ldg(&proj_b[lane])), b1 = pk2(__ldg(&proj_b[lane + 32]));
#pragma unroll
        for (int p = 0; p < 4; p++) { a0[p] = b0; a1[p] = b1; }
#pragma unroll 4
        for (int k4 = 0; k4 < 64; k4 += 4) {
            float4 wa = *(const float4*)&WB[lane * 68 + k4];
            float4 wb = *(const float4*)&WB[(lane + 32) * 68 + k4];
            float wav[4] = {wa.x, wa.y, wa.z, wa.w};
            float wbv[4] = {wb.x, wb.y, wb.z, wb.w};
#pragma unroll
            for (int kk = 0; kk < 4; kk++) {
                int k = k4 + kk;
                ulonglong2 xa = *(const ulonglong2*)&AR[k * 68 + t0];
                ulonglong2 xb = *(const ulonglong2*)&AR[k * 68 + t0 + 4];
                u64 w0 = pk2(wav[kk]);
                u64 w1 = pk2(wbv[kk]);
                fma2(a0[0], xa.x, w0); fma2(a0[1], xa.y, w0);
                fma2(a0[2], xb.x, w0); fma2(a0[3], xb.y, w0);
                fma2(a1[0], xa.x, w1); fma2(a1[1], xa.y, w1);
                fma2(a1[2], xb.x, w1); fma2(a1[3], xb.y, w1);
            }
        }
#pragma unroll
        for (int p = 0; p < 4; p++) {
            float2 v0 = up2(a0[p]), v1 = up2(a1[p]);
            x2c0[2 * p] += v0.x; x2c0[2 * p + 1] += v0.y;
            x2c1[2 * p] += v1.x; x2c1[2 * p + 1] += v1.y;
        }
    }
    __syncthreads();

    for (int idx = tid; idx < 64 * 64; idx += 256) {
        int o = idx >> 6, k = idx & 63;
        cpa4(&WB[o * 68 + k], &fc1_w[idx]);
    }
    cp_commit();

    // ---- LN2 -> XN ----
    {
        float lw0 = ln_w[lane], lb0 = ln_b[lane];
        float lw1 = ln_w[lane + 32], lb1 = ln_b[lane + 32];
#pragma unroll
        for (int t = 0; t < 8; t++) {
            float c0 = x2c0[t], c1 = x2c1[t];
            float s  = warp_sum(c0 + c1);
            float sq = warp_sum(c0 * c0 + c1 * c1);
            float m  = s * (1.0f / 64.0f);
            float r  = rsqrtf(sq * (1.0f / 64.0f) - m * m + 1e-5f);
            XN[lane * 68 + t0 + t]        = (c0 - m) * r * lw0 + lb0;
            XN[(lane + 32) * 68 + t0 + t] = (c1 - m) * r * lw1 + lb1;
        }
    }
    u64 f0[4], f1[4];
    {
        float bf0 = __ldg(&fc2_b[lane]), bf1 = __ldg(&fc2_b[lane + 32]);
#pragma unroll
        for (int p = 0; p < 4; p++) {
            f0[p] = pk2f(bf0 + x2c0[2 * p], bf0 + x2c0[2 * p + 1]);
            f1[p] = pk2f(bf1 + x2c1[2 * p], bf1 + x2c1[2 * p + 1]);
        }
    }
    cp_wait0();
    __syncthreads();

#pragma unroll 1
    for (int q = 0; q < 4; q++) {
        u64 acc[2][4];
#pragma unroll
        for (int jj = 0; jj < 2; jj++) {
            u64 bq = pk2(BS[64 * q + 32 * jj + lane]);
#pragma unroll
            for (int p = 0; p < 4; p++) acc[jj][p] = bq;
        }
#pragma unroll 4
        for (int k4 = 0; k4 < 64; k4 += 4) {
            float4 wa = *(const float4*)&WB[lane * 68 + k4];
            float4 wb = *(const float4*)&WB[(lane + 32) * 68 + k4];
            float wav[4] = {wa.x, wa.y, wa.z, wa.w};
            float wbv[4] = {wb.x, wb.y, wb.z, wb.w};
#pragma unroll
            for (int kk = 0; kk < 4; kk++) {
                int k = k4 + kk;
                ulonglong2 xa = *(const ulonglong2*)&XN[k * 68 + t0];
                ulonglong2 xb = *(const ulonglong2*)&XN[k * 68 + t0 + 4];
                u64 w0 = pk2(wav[kk]);
                u64 w1 = pk2(wbv[kk]);
                fma2(acc[0][0], xa.x, w0); fma2(acc[0][1], xa.y, w0);
                fma2(acc[0][2], xb.x, w0); fma2(acc[0][3], xb.y, w0);
                fma2(acc[1][0], xa.x, w1); fma2(acc[1][1], xa.y, w1);
                fma2(acc[1][2], xb.x, w1); fma2(acc[1][3], xb.y, w1);
            }
        }
#pragma unroll
        for (int jj = 0; jj < 2; jj++) {
#pragma unroll
            for (int p = 0; p < 4; p++) {
                float2 v = up2(acc[jj][p]);
                v.x = gelu_f(v.x);
                v.y = gelu_f(v.y);
                *(float2*)&AR[(lane + 32 * jj) * 68 + t0 + 2 * p] = v;
            }
        }
        __syncwarp();
        __syncthreads();
        if (q < 3) {
            const float* w1q = fc1_w + (size_t)(64 * (q + 1)) * 64;
            for (int idx = tid; idx < 64 * 64; idx += 256) {
                int o = idx >> 6, k = idx & 63;
                cpa4(&WB[o * 68 + k], &w1q[idx]);
            }
            cp_commit();
        }
        const float* w2r = &g_w2t[(size_t)(64 * q) * 64];
#pragma unroll 4
        for (int kk = 0; kk < 64; kk++) {
            ulonglong2 xa = *(const ulonglong2*)&AR[kk * 68 + t0];
            ulonglong2 xb = *(const ulonglong2*)&AR[kk * 68 + t0 + 4];
            u64 w0 = pk2(__ldg(&w2r[kk * 64 + lane]));
            u64 w1 = pk2(__ldg(&w2r[kk * 64 + lane + 32]));
            fma2(f0[0], xa.x, w0); fma2(f0[1], xa.y, w0);
            fma2(f0[2], xb.x, w0); fma2(f0[3], xb.y, w0);
            fma2(f1[0], xa.x, w1); fma2(f1[1], xa.y, w1);
            fma2(f1[2], xb.x, w1); fma2(f1[3], xb.y, w1);
        }
        if (q < 3) {
            cp_wait0();
            __syncthreads();
        }
    }
    __syncthreads();

#pragma unroll
    for (int p = 0; p < 4; p++) {
        float2 v0 = up2(f0[p]), v1 = up2(f1[p]);
        *(float2*)&AR[lane * 68 + t0 + 2 * p]        = v0;
        *(float2*)&AR[(lane + 32) * 68 + t0 + 2 * p] = v1;
    }
    __syncthreads();
    float* oo = out + (size_t)n * CH * HW + hw0;
    for (int idx = tid; idx < 64 * 64; idx += 256) {
        int c = idx >> 6, t = idx & 63;
        oo[(size_t)c * HW + t] = AR[c * 68 + t];
    }
}

// ---------------------------------------------------------------------------
extern "C" void kernel_launch(void* const* d_in, const int* in_sizes, int n_in,
                              void* d_out, int out_size)
{
    const float* x      = (const float*)d_in[0];
    const float* qkv_w  = (const float*)d_in[1];
    const float* qkv_b  = (const float*)d_in[2];
    const float* proj_w = (const float*)d_in[3];
    const float* proj_b = (const float*)d_in[4];
    const float* rpb    = (const float*)d_in[5];
    const float* ln1_w  = (const float*)d_in[6];
    const float* ln1_b  = (const float*)d_in[7];
    const float* ln2_w  = (const float*)d_in[8];
    const float* ln2_b  = (const float*)d_in[9];
    const float* fc1_w  = (const float*)d_in[10];
    const float* fc1_b  = (const float*)d_in[11];
    const float* fc2_w  = (const float*)d_in[12];
    const float* fc2_b  = (const float*)d_in[13];
    float* out = (float*)d_out;

    const int smB = (4352 + C3 * 70) * 4;
    const int smC = (196 * 33 * 2 + 64 * 32 + 172 + 8 * 52) * 4;
    const int smM = (4352 + 4352 + 4352 + 256) * 4;

    cudaFuncSetAttribute(k_ln_qkv, cudaFuncAttributeMaxDynamicSharedMemorySize, smB);
    cudaFuncSetAttribute(k_attn,   cudaFuncAttributeMaxDynamicSharedMemorySize, smC);
    cudaFuncSetAttribute(k_mlp,    cudaFuncAttributeMaxDynamicSharedMemorySize, smM);

    k_ln_qkv<<<512, 256, smB>>>(x, qkv_w, qkv_b, ln1_w, ln1_b, fc2_w);
    k_attn<<<1024, 256, smC>>>(rpb);
    k_mlp<<<512, 256, smM>>>(x, proj_w, proj_b, fc1_w, fc1_b, fc2_b,
                             ln2_w, ln2_b, out);
}